// round 4
// baseline (speedup 1.0000x reference)
#include <cuda_runtime.h>
#include <cstdint>

// ---------------------------------------------------------------------------
// Fused edge-MLP:
//   pair = [x1[src], x2[dst]]            (E x 256)
//   h1 = relu(pair @ W1 + b1)            (E x 128)
//   h2 = relu(h1 @ W2 + b2)              (E x 128)
//   out = h2 @ W3 + b3                   (E x 1)
//
// One CTA = 128 edges. 256 threads, each owns an 8x8 output tile kept as
// packed f32x2 accumulators (fma.rn.f32x2 -> SASS FFMA2, 2x FFMA throughput).
// NOTE: edge_index is int32 (JAX downgrades int64 without x64 mode).
// ---------------------------------------------------------------------------

using ull = unsigned long long;

#define TILE_M   128
#define NT       256
#define SA_LD    256                      // pair tile leading dim (floats)
#define SH_LD    136                      // h1 tile leading dim (padded)
#define SA_FLOATS (128 * 256)             // 32768 floats = 128 KB
#define SW_FLOATS (16 * 128)              // one 16x128 weight chunk = 8 KB
#define SMEM_FLOATS (SA_FLOATS + 2 * SW_FLOATS)   // 36864 floats
#define SMEM_BYTES  (SMEM_FLOATS * 4)             // 147456 bytes

__device__ __forceinline__ void fma2(ull& d, ull a, ull b) {
    asm("fma.rn.f32x2 %0, %1, %2, %0;" : "+l"(d) : "l"(a), "l"(b));
}
__device__ __forceinline__ ull dup2(float a) {
    ull d;
    asm("mov.b64 %0, {%1, %1};" : "=l"(d) : "f"(a));
    return d;
}
__device__ __forceinline__ float2 unpack2(ull v) {
    float2 f;
    asm("mov.b64 {%0, %1}, %2;" : "=f"(f.x), "=f"(f.y) : "l"(v));
    return f;
}

// Compute 16 k-steps of the 128x128(xK) tile GEMM.
// aBase points at this thread's first row (rowbase) of the activation tile.
// sw holds a 16x128 fp32 weight chunk (k-major).
template <int LD>
__device__ __forceinline__ void gemm_chunk16(const float* __restrict__ aBase,
                                             int kt,
                                             const float* __restrict__ sw,
                                             int colbase,
                                             ull acc[8][4]) {
#pragma unroll
    for (int k = 0; k < 16; ++k) {
        ull a2[8];
#pragma unroll
        for (int i = 0; i < 8; ++i)
            a2[i] = dup2(aBase[i * LD + kt + k]);   // broadcast LDS
        const ull* bp = reinterpret_cast<const ull*>(sw + k * 128 + colbase);
        ull b0 = bp[0], b1 = bp[1], b2 = bp[2], b3 = bp[3];
#pragma unroll
        for (int i = 0; i < 8; ++i) {
            fma2(acc[i][0], a2[i], b0);
            fma2(acc[i][1], a2[i], b1);
            fma2(acc[i][2], a2[i], b2);
            fma2(acc[i][3], a2[i], b3);
        }
    }
}

__global__ __launch_bounds__(NT, 1)
void edge_mlp_kernel(const float* __restrict__ x1,
                     const float* __restrict__ x2,
                     const int* __restrict__ ei,
                     const float* __restrict__ W1, const float* __restrict__ b1,
                     const float* __restrict__ W2, const float* __restrict__ b2,
                     const float* __restrict__ W3, const float* __restrict__ b3,
                     float* __restrict__ out, int E) {
    extern __shared__ float smem[];
    float* sWbuf0 = smem + SA_FLOATS;
    float* sWbuf1 = smem + SA_FLOATS + SW_FLOATS;

    const int tid  = threadIdx.x;
    const int lane = tid & 31;
    const int wrp  = tid >> 5;
    const int tx   = tid & 15;
    const int ty   = tid >> 4;
    const int rowbase = ty * 8;
    const int colbase = tx * 8;
    const long long e0 = (long long)blockIdx.x * TILE_M;

    // Weight-chunk staging coordinates: 16 rows x 128 cols, thread loads 8 floats.
    const int wr = tid >> 4;           // chunk row 0..15
    const int wc = (tid & 15) * 8;     // col offset

    // ---------------- Phase A: gather pair tile into SMEM -----------------
    // Warp w handles edges m = w, w+8, ... Each warp reads the whole 512B row
    // of x1[src] / x2[dst] coalesced (32 lanes x float4).
    for (int m = wrp; m < TILE_M; m += 8) {
        long long e = e0 + m;
        if (e < E) {
            long long s = ei[e];            // int32 indices
            long long t = ei[(long long)E + e];
            float4 v1 = reinterpret_cast<const float4*>(x1 + s * 128)[lane];
            float4 v2 = reinterpret_cast<const float4*>(x2 + t * 128)[lane];
            reinterpret_cast<float4*>(smem + m * SA_LD)[lane]       = v1;
            reinterpret_cast<float4*>(smem + m * SA_LD + 128)[lane] = v2;
        }
    }

    // Stage W1 chunk 0 into buffer 0.
    float4 s0 = *reinterpret_cast<const float4*>(W1 + wr * 128 + wc);
    float4 s1 = *reinterpret_cast<const float4*>(W1 + wr * 128 + wc + 4);
    *reinterpret_cast<float4*>(sWbuf0 + wr * 128 + wc)     = s0;
    *reinterpret_cast<float4*>(sWbuf0 + wr * 128 + wc + 4) = s1;
    __syncthreads();

    // ---------------- Phase B: layer 1 GEMM (K = 256, 16 chunks) ----------
    ull acc[8][4];
#pragma unroll
    for (int i = 0; i < 8; ++i)
#pragma unroll
        for (int j = 0; j < 4; ++j) acc[i][j] = 0ULL;

    const float* aBase = smem + rowbase * SA_LD;
    for (int ct = 0; ct < 16; ++ct) {
        if (ct + 1 < 16) {   // issue next-chunk global loads (hidden by compute)
            const float* src = W1 + (ct + 1) * 16 * 128;
            s0 = *reinterpret_cast<const float4*>(src + wr * 128 + wc);
            s1 = *reinterpret_cast<const float4*>(src + wr * 128 + wc + 4);
        }
        gemm_chunk16<SA_LD>(aBase, ct * 16, (ct & 1) ? sWbuf1 : sWbuf0, colbase, acc);
        if (ct + 1 < 16) {   // safe: that buffer's readers finished 2 bars ago
            float* dst = ((ct + 1) & 1) ? sWbuf1 : sWbuf0;
            *reinterpret_cast<float4*>(dst + wr * 128 + wc)     = s0;
            *reinterpret_cast<float4*>(dst + wr * 128 + wc + 4) = s1;
        }
        __syncthreads();
    }

    // ---------------- Phase C: epilogue 1 -> h1 in SMEM (reuses sA) -------
    float* sH = smem;   // pair tile fully consumed; bar above guarantees safety
    {
        float2 bb[4];
#pragma unroll
        for (int j = 0; j < 4; ++j)
            bb[j] = *reinterpret_cast<const float2*>(b1 + colbase + 2 * j);
#pragma unroll
        for (int i = 0; i < 8; ++i) {
            float* hrow = sH + (rowbase + i) * SH_LD + colbase;
#pragma unroll
            for (int j = 0; j < 4; ++j) {
                float2 v = unpack2(acc[i][j]);
                v.x = fmaxf(v.x + bb[j].x, 0.0f);
                v.y = fmaxf(v.y + bb[j].y, 0.0f);
                *reinterpret_cast<float2*>(hrow + 2 * j) = v;
            }
        }
    }

    // Stage W2 chunk 0.
    s0 = *reinterpret_cast<const float4*>(W2 + wr * 128 + wc);
    s1 = *reinterpret_cast<const float4*>(W2 + wr * 128 + wc + 4);
    *reinterpret_cast<float4*>(sWbuf0 + wr * 128 + wc)     = s0;
    *reinterpret_cast<float4*>(sWbuf0 + wr * 128 + wc + 4) = s1;
    __syncthreads();   // h1 + W2 chunk 0 visible

    // ---------------- Phase D: layer 2 GEMM (K = 128, 8 chunks) -----------
#pragma unroll
    for (int i = 0; i < 8; ++i)
#pragma unroll
        for (int j = 0; j < 4; ++j) acc[i][j] = 0ULL;

    const float* aBase2 = sH + rowbase * SH_LD;
    for (int ct = 0; ct < 8; ++ct) {
        if (ct + 1 < 8) {
            const float* src = W2 + (ct + 1) * 16 * 128;
            s0 = *reinterpret_cast<const float4*>(src + wr * 128 + wc);
            s1 = *reinterpret_cast<const float4*>(src + wr * 128 + wc + 4);
        }
        gemm_chunk16<SH_LD>(aBase2, ct * 16, (ct & 1) ? sWbuf1 : sWbuf0, colbase, acc);
        if (ct + 1 < 8) {
            float* dst = ((ct + 1) & 1) ? sWbuf1 : sWbuf0;
            *reinterpret_cast<float4*>(dst + wr * 128 + wc)     = s0;
            *reinterpret_cast<float4*>(dst + wr * 128 + wc + 4) = s1;
        }
        __syncthreads();
    }

    // ---------------- Phase E: layer 3 (dot with W3) + reduction ----------
    float2 b2v[4], w3v[4];
#pragma unroll
    for (int j = 0; j < 4; ++j) {
        b2v[j] = *reinterpret_cast<const float2*>(b2 + colbase + 2 * j);
        w3v[j] = *reinterpret_cast<const float2*>(W3 + colbase + 2 * j);
    }
    float p[8];
#pragma unroll
    for (int i = 0; i < 8; ++i) {
        float acc_p = 0.0f;
#pragma unroll
        for (int j = 0; j < 4; ++j) {
            float2 v = unpack2(acc[i][j]);
            float h0 = fmaxf(v.x + b2v[j].x, 0.0f);
            float h1v = fmaxf(v.y + b2v[j].y, 0.0f);
            acc_p += h0 * w3v[j].x + h1v * w3v[j].y;
        }
        p[i] = acc_p;
    }

    // Reduce 16 column-partials per edge via SMEM (reuses weight buffers:
    // last reader passed the loop-final __syncthreads above).
    float* sRed = smem + SA_FLOATS;          // 128 x 17 floats
#pragma unroll
    for (int i = 0; i < 8; ++i)
        sRed[(rowbase + i) * 17 + tx] = p[i];
    __syncthreads();

    if (tid < TILE_M) {
        long long e = e0 + tid;
        if (e < E) {
            float s = 0.0f;
#pragma unroll
            for (int t = 0; t < 16; ++t) s += sRed[tid * 17 + t];
            out[e] = s + b3[0];
        }
    }
}

extern "C" void kernel_launch(void* const* d_in, const int* in_sizes, int n_in,
                              void* d_out, int out_size) {
    const float* x1 = (const float*)d_in[0];
    const float* x2 = (const float*)d_in[1];
    const int*   ei = (const int*)d_in[2];          // int32 [2, E]
    const float* W1 = (const float*)d_in[3];        // [256,128]
    const float* b1 = (const float*)d_in[4];        // [128]
    const float* W2 = (const float*)d_in[5];        // [128,128]
    const float* b2 = (const float*)d_in[6];        // [128]
    const float* W3 = (const float*)d_in[7];        // [128,1]
    const float* b3 = (const float*)d_in[8];        // [1]
    float*       out = (float*)d_out;

    int E = in_sizes[2] / 2;
    int grid = (E + TILE_M - 1) / TILE_M;

    cudaFuncSetAttribute(edge_mlp_kernel,
                         cudaFuncAttributeMaxDynamicSharedMemorySize, SMEM_BYTES);
    edge_mlp_kernel<<<grid, NT, SMEM_BYTES>>>(x1, x2, ei, W1, b1, W2, b2, W3, b3,
                                              out, E);
}

// round 6
// speedup vs baseline: 1.9609x; 1.9609x over previous
#include <cuda_runtime.h>
#include <cuda_bf16.h>
#include <cstdint>

// ---------------------------------------------------------------------------
// Fused edge-MLP. Two device code paths:
//  * sm_103a (feature macro __CUDA_ARCH_FEAT_SM103_ALL): tcgen05 bf16 tensor
//    cores with a 2-term bf16 split (Ah*Bh + Al*Bh + Ah*Bl, fp32 accum) for
//    fp32-class accuracy.
//  * plain sm_103 / other targets: fp32 FFMA2 (fma.rn.f32x2) fallback
//    (the proven R4 kernel) so the harness's compute_103 pass still compiles.
// ---------------------------------------------------------------------------

#if defined(__CUDA_ARCH__) && defined(__CUDA_ARCH_FEAT_SM103_ALL)
#define EDGE_USE_TC 1
#else
#define EDGE_USE_TC 0
#endif

using ull = unsigned long long;

#define NT      256
#define TILE_M  128

// ---------------- tc-path SMEM byte offsets ----------------
#define SMEM_AH      0        // A hi: 4 blocks x 16KB = 64KB (reused for h1 hi)
#define SMEM_AL      65536    // A lo: 64KB (reused for h1 lo)
#define SMEM_W       131072   // weight buffer: 64KB
#define SMEM_CONST   196608   // b1[128] | b2[128] | W3[128] | b3  (fp32)
#define SMEM_TMEMPTR 198144
#define SMEM_MBAR    198152
#define SMEM_TOTAL   198176

// idesc kind::f16: F32 accum (1<<4), BF16 a (1<<7), BF16 b (1<<10),
// N=128 ((128/8)<<17), M=128 ((128/16)<<24)
#define IDESC   0x8200490u

// ---------------- fallback-path SMEM layout (floats) ----------------
#define SA_LD    256
#define SH_LD    136
#define SA_FLOATS (128 * 256)
#define SW_FLOATS (16 * 128)

// Prepared weights (transposed to [N,K] rows, bf16 hi/lo, SW128-swizzled blocks)
__device__ __align__(16) __nv_bfloat16 g_W1h[32768];
__device__ __align__(16) __nv_bfloat16 g_W1l[32768];
__device__ __align__(16) __nv_bfloat16 g_W2h[16384];
__device__ __align__(16) __nv_bfloat16 g_W2l[16384];

__device__ __forceinline__ int sw128(int off) { return off ^ ((off >> 3) & 0x70); }

// =================== helpers: fallback (all targets) =======================

__device__ __forceinline__ void fma2(ull& d, ull a, ull b) {
    asm("fma.rn.f32x2 %0, %1, %2, %0;" : "+l"(d) : "l"(a), "l"(b));
}
__device__ __forceinline__ ull dup2(float a) {
    ull d;
    asm("mov.b64 %0, {%1, %1};" : "=l"(d) : "f"(a));
    return d;
}
__device__ __forceinline__ float2 unpack2(ull v) {
    float2 f;
    asm("mov.b64 {%0, %1}, %2;" : "=f"(f.x), "=f"(f.y) : "l"(v));
    return f;
}

template <int LD>
__device__ __forceinline__ void gemm_chunk16(const float* __restrict__ aBase,
                                             int kt,
                                             const float* __restrict__ sw,
                                             int colbase,
                                             ull acc[8][4]) {
#pragma unroll
    for (int k = 0; k < 16; ++k) {
        ull a2[8];
#pragma unroll
        for (int i = 0; i < 8; ++i)
            a2[i] = dup2(aBase[i * LD + kt + k]);
        const ull* bp = reinterpret_cast<const ull*>(sw + k * 128 + colbase);
        ull b0 = bp[0], b1 = bp[1], b2 = bp[2], b3 = bp[3];
#pragma unroll
        for (int i = 0; i < 8; ++i) {
            fma2(acc[i][0], a2[i], b0);
            fma2(acc[i][1], a2[i], b1);
            fma2(acc[i][2], a2[i], b2);
            fma2(acc[i][3], a2[i], b3);
        }
    }
}

// =================== helpers: tcgen05 (sm_103a pass only) ==================

#if EDGE_USE_TC

__device__ __forceinline__ uint32_t smem_u32_of(const void* p) {
    uint32_t a;
    asm("{ .reg .u64 t; cvta.to.shared.u64 t, %1; cvt.u32.u64 %0, t; }"
        : "=r"(a) : "l"(p));
    return a;
}

__device__ __forceinline__ uint32_t elect_one() {
    uint32_t pred;
    asm volatile("{ .reg .pred p; elect.sync _|p, 0xFFFFFFFF; selp.b32 %0, 1, 0, p; }"
                 : "=r"(pred));
    return pred;
}

__device__ __forceinline__ uint64_t smem_desc(uint32_t addr) {
    // SW128, Blackwell version=1, SBO=64, LBO=1
    return 0x4000404000010000ULL | ((uint64_t)(addr >> 4) & 0x3FFF);
}

__device__ __forceinline__ void mma_f16_ss(uint32_t d_tmem, uint64_t a_desc,
                                           uint64_t b_desc, uint32_t en) {
    asm volatile(
        "{\n\t.reg .pred p;\n\tsetp.ne.u32 p, %4, 0;\n\t"
        "tcgen05.mma.cta_group::1.kind::f16 [%0], %1, %2, %3, {%5,%5,%5,%5}, p;\n\t}"
        :: "r"(d_tmem), "l"(a_desc), "l"(b_desc), "r"(IDESC), "r"(en), "r"(0u)
        : "memory");
}

#define TCGEN05_ALLOC(sa, n) \
    asm volatile("tcgen05.alloc.cta_group::1.sync.aligned.shared::cta.b32 [%0], %1;" \
                 :: "r"((uint32_t)(sa)), "r"((uint32_t)(n)) : "memory")
#define TCGEN05_DEALLOC(t, n) \
    asm volatile("tcgen05.dealloc.cta_group::1.sync.aligned.b32 %0, %1;" \
                 :: "r"(t), "r"((uint32_t)(n)))
#define TCGEN05_COMMIT(mb) \
    asm volatile("tcgen05.commit.cta_group::1.mbarrier::arrive::one.shared::cluster.b64 [%0];" \
                 :: "r"((uint32_t)(mb)) : "memory")
#define TCGEN05_WAIT_LD() asm volatile("tcgen05.wait::ld.sync.aligned;" ::: "memory")
#define TCGEN05_FENCE_AFTER() asm volatile("tcgen05.fence::after_thread_sync;" ::: "memory")
#define FENCE_ASYNC() asm volatile("fence.proxy.async.shared::cta;" ::: "memory")
#define MBARRIER_INIT(mb, c) \
    asm volatile("mbarrier.init.shared.b64 [%0], %1;" :: "r"((uint32_t)(mb)), "r"((uint32_t)(c)) : "memory")
#define MBARRIER_INVAL(mb) \
    asm volatile("mbarrier.inval.shared.b64 [%0];" :: "r"((uint32_t)(mb)) : "memory")

#define MBARRIER_WAIT_PARITY(mb, ph) do {                                          \
    uint32_t _m = (uint32_t)(mb), _p = (uint32_t)(ph), _done;                      \
    asm volatile("{\n\t.reg .pred p;\n\t"                                          \
        "mbarrier.try_wait.parity.acquire.cta.shared::cta.b64 p, [%1], %2;\n\t"    \
        "selp.b32 %0, 1, 0, p;\n\t}" : "=r"(_done) : "r"(_m), "r"(_p) : "memory"); \
    if (!_done) {                                                                  \
        asm volatile("{\n\t.reg .pred P1;\n\t"                                     \
        "WL_%=:\n\t"                                                               \
        "mbarrier.try_wait.parity.acquire.cta.shared::cta.b64 P1, [%0], %1, 0x989680;\n\t" \
        "@P1 bra.uni WD_%=;\n\t"                                                   \
        "bra.uni WL_%=;\n\t"                                                       \
        "WD_%=:\n\t}" :: "r"(_m), "r"(_p) : "memory");                             \
    }                                                                              \
} while (0)

#define LDTM_X32(r, a)                                                             \
    asm volatile("tcgen05.ld.sync.aligned.32x32b.x32.b32 "                         \
        "{%0,%1,%2,%3,%4,%5,%6,%7,%8,%9,%10,%11,%12,%13,%14,%15,"                  \
        "%16,%17,%18,%19,%20,%21,%22,%23,%24,%25,%26,%27,%28,%29,%30,%31}, [%32];" \
        : "=r"((r)[0]),"=r"((r)[1]),"=r"((r)[2]),"=r"((r)[3]),                     \
          "=r"((r)[4]),"=r"((r)[5]),"=r"((r)[6]),"=r"((r)[7]),                     \
          "=r"((r)[8]),"=r"((r)[9]),"=r"((r)[10]),"=r"((r)[11]),                   \
          "=r"((r)[12]),"=r"((r)[13]),"=r"((r)[14]),"=r"((r)[15]),                 \
          "=r"((r)[16]),"=r"((r)[17]),"=r"((r)[18]),"=r"((r)[19]),                 \
          "=r"((r)[20]),"=r"((r)[21]),"=r"((r)[22]),"=r"((r)[23]),                 \
          "=r"((r)[24]),"=r"((r)[25]),"=r"((r)[26]),"=r"((r)[27]),                 \
          "=r"((r)[28]),"=r"((r)[29]),"=r"((r)[30]),"=r"((r)[31])                  \
        : "r"(a))

__device__ __forceinline__ uint32_t pack_bf2(float lo_val, float hi_val) {
    __nv_bfloat162 t = __floats2bfloat162_rn(lo_val, hi_val);
    return *reinterpret_cast<uint32_t*>(&t);
}

#endif  // EDGE_USE_TC

// ------------------------------ prep kernel -------------------------------
// Transpose W1 [256,128] / W2 [128,128] to B-operand layout ([N=128 rows, K]),
// split to bf16 hi/lo, store SW128-swizzled in [128 x 64bf16] K-chunk blocks.
__global__ void prep_kernel(const float* __restrict__ W1,
                            const float* __restrict__ W2) {
    int i = blockIdx.x * blockDim.x + threadIdx.x;
    if (i < 32768) {
        int k = i >> 7, n = i & 127;
        float w = W1[i];
        __nv_bfloat16 hi = __float2bfloat16_rn(w);
        __nv_bfloat16 lo = __float2bfloat16_rn(w - __bfloat162float(hi));
        int c = k >> 6, kk = k & 63;
        int idx = (c * 16384 + sw128(n * 128 + kk * 2)) >> 1;
        g_W1h[idx] = hi;
        g_W1l[idx] = lo;
    } else if (i < 49152) {
        int j = i - 32768;
        int k = j >> 7, n = j & 127;
        float w = W2[j];
        __nv_bfloat16 hi = __float2bfloat16_rn(w);
        __nv_bfloat16 lo = __float2bfloat16_rn(w - __bfloat162float(hi));
        int c = k >> 6, kk = k & 63;
        int idx = (c * 16384 + sw128(n * 128 + kk * 2)) >> 1;
        g_W2h[idx] = hi;
        g_W2l[idx] = lo;
    }
}

// ------------------------------ main kernel -------------------------------

__global__ __launch_bounds__(NT, 1)
void edge_mlp_kernel(const float* __restrict__ x1,
                     const float* __restrict__ x2,
                     const int* __restrict__ ei,
                     const float* __restrict__ W1g, const float* __restrict__ b1g,
                     const float* __restrict__ W2g, const float* __restrict__ b2g,
                     const float* __restrict__ W3g, const float* __restrict__ b3g,
                     float* __restrict__ out, int E) {
    extern __shared__ char smem_raw[];

#if EDGE_USE_TC
    // ======================= tcgen05 tensor-core path =======================
    char* smem = smem_raw;
    const uint32_t sb = smem_u32_of(smem);
    const int tid  = threadIdx.x;
    const int lane = tid & 31;
    const int wid  = tid >> 5;
    const int e0   = blockIdx.x * TILE_M;

    if (wid == 0) TCGEN05_ALLOC(sb + SMEM_TMEMPTR, 256);
    if (tid == 0) MBARRIER_INIT(sb + SMEM_MBAR, 1);
    __syncthreads();
    uint32_t tmem;
    asm volatile("ld.shared.b32 %0, [%1];" : "=r"(tmem) : "r"(sb + SMEM_TMEMPTR));
    const uint32_t tD1 = tmem, tD2 = tmem + 128;

    // --- Phase 0: gather + bf16-split pair tile; stage consts; copy W1h ---
    {
        const int blk1 = lane >> 4;
        const int joff = 8 * (lane & 15);
        for (int m = wid; m < TILE_M; m += 8) {
            int e = e0 + m;
            if (e < E) {
                long long s = ei[e];
                long long t = ei[(long long)E + e];
                float4 v1 = reinterpret_cast<const float4*>(x1 + s * 128)[lane];
                float4 v2 = reinterpret_cast<const float4*>(x2 + t * 128)[lane];
                int off = sw128(m * 128 + joff);
                {
                    __nv_bfloat162 h01 = __floats2bfloat162_rn(v1.x, v1.y);
                    __nv_bfloat162 h23 = __floats2bfloat162_rn(v1.z, v1.w);
                    float r0 = v1.x - __bfloat162float(h01.x);
                    float r1 = v1.y - __bfloat162float(h01.y);
                    float r2 = v1.z - __bfloat162float(h23.x);
                    float r3 = v1.w - __bfloat162float(h23.y);
                    uint2 hh = make_uint2(*(uint32_t*)&h01, *(uint32_t*)&h23);
                    uint2 ll = make_uint2(pack_bf2(r0, r1), pack_bf2(r2, r3));
                    *reinterpret_cast<uint2*>(smem + SMEM_AH + blk1 * 16384 + off) = hh;
                    *reinterpret_cast<uint2*>(smem + SMEM_AL + blk1 * 16384 + off) = ll;
                }
                {
                    __nv_bfloat162 h01 = __floats2bfloat162_rn(v2.x, v2.y);
                    __nv_bfloat162 h23 = __floats2bfloat162_rn(v2.z, v2.w);
                    float r0 = v2.x - __bfloat162float(h01.x);
                    float r1 = v2.y - __bfloat162float(h01.y);
                    float r2 = v2.z - __bfloat162float(h23.x);
                    float r3 = v2.w - __bfloat162float(h23.y);
                    uint2 hh = make_uint2(*(uint32_t*)&h01, *(uint32_t*)&h23);
                    uint2 ll = make_uint2(pack_bf2(r0, r1), pack_bf2(r2, r3));
                    *reinterpret_cast<uint2*>(smem + SMEM_AH + (2 + blk1) * 16384 + off) = hh;
                    *reinterpret_cast<uint2*>(smem + SMEM_AL + (2 + blk1) * 16384 + off) = ll;
                }
            }
        }
        if (tid < 128) {
            ((float*)(smem + SMEM_CONST))[tid]        = b1g[tid];
            ((float*)(smem + SMEM_CONST + 512))[tid]  = b2g[tid];
            ((float*)(smem + SMEM_CONST + 1024))[tid] = W3g[tid];
        }
        if (tid == 0) ((float*)(smem + SMEM_CONST + 1536))[0] = b3g[0];
        const uint4* src = reinterpret_cast<const uint4*>(g_W1h);
        uint4* dst = reinterpret_cast<uint4*>(smem + SMEM_W);
        for (int i = tid; i < 4096; i += NT) dst[i] = src[i];
    }
    FENCE_ASYNC();
    __syncthreads();

    // --- MMA layer 1: Ah*Wh + Al*Wh ---
    if (wid == 0 && elect_one()) {
        for (int pass = 0; pass < 2; ++pass) {
            uint32_t abase = sb + (pass ? SMEM_AL : SMEM_AH);
            for (int c = 0; c < 4; ++c) {
                uint64_t ad = smem_desc(abase + c * 16384);
                uint64_t bd = smem_desc(sb + SMEM_W + c * 16384);
                for (int k = 0; k < 4; ++k)
                    mma_f16_ss(tD1, ad + k * 2, bd + k * 2,
                               (pass == 0 && c == 0 && k == 0) ? 0u : 1u);
            }
        }
        TCGEN05_COMMIT(sb + SMEM_MBAR);
    }
    MBARRIER_WAIT_PARITY(sb + SMEM_MBAR, 0);

    // --- swap to W1 lo, Ah*Wl ---
    {
        const uint4* src = reinterpret_cast<const uint4*>(g_W1l);
        uint4* dst = reinterpret_cast<uint4*>(smem + SMEM_W);
        for (int i = tid; i < 4096; i += NT) dst[i] = src[i];
    }
    FENCE_ASYNC();
    __syncthreads();
    if (wid == 0 && elect_one()) {
        for (int c = 0; c < 4; ++c) {
            uint64_t ad = smem_desc(sb + SMEM_AH + c * 16384);
            uint64_t bd = smem_desc(sb + SMEM_W + c * 16384);
            for (int k = 0; k < 4; ++k)
                mma_f16_ss(tD1, ad + k * 2, bd + k * 2, 1u);
        }
        TCGEN05_COMMIT(sb + SMEM_MBAR);
    }
    MBARRIER_WAIT_PARITY(sb + SMEM_MBAR, 1);
    TCGEN05_FENCE_AFTER();

    // --- Epilogue 1: h1 = relu(D1+b1) -> split to SMEM blocks 0..1;
    //     warps 4-7 stage W2 hi concurrently ---
    if (wid < 4) {
        const int r = (wid << 5) + lane;
        const float* b1s = (const float*)(smem + SMEM_CONST);
        for (int ch = 0; ch < 4; ++ch) {
            uint32_t d[32];
            LDTM_X32(d, tD1 + ch * 32);
            TCGEN05_WAIT_LD();
            const int colbase = ch * 32;
            char* hb = smem + SMEM_AH + (colbase >> 6) * 16384;
            char* lb = smem + SMEM_AL + (colbase >> 6) * 16384;
#pragma unroll
            for (int p = 0; p < 16; ++p) {
                int col = colbase + 2 * p;
                float v0 = fmaxf(__uint_as_float(d[2 * p])     + b1s[col],     0.0f);
                float v1 = fmaxf(__uint_as_float(d[2 * p + 1]) + b1s[col + 1], 0.0f);
                __nv_bfloat162 h = __floats2bfloat162_rn(v0, v1);
                float r0 = v0 - __bfloat162float(h.x);
                float r1 = v1 - __bfloat162float(h.y);
                int off = sw128(r * 128 + (col & 63) * 2);
                *reinterpret_cast<uint32_t*>(hb + off) = *(uint32_t*)&h;
                *reinterpret_cast<uint32_t*>(lb + off) = pack_bf2(r0, r1);
            }
        }
    } else {
        const uint4* src = reinterpret_cast<const uint4*>(g_W2h);
        uint4* dst = reinterpret_cast<uint4*>(smem + SMEM_W);
        for (int i = tid - 128; i < 2048; i += 128) dst[i] = src[i];
    }
    FENCE_ASYNC();
    __syncthreads();

    // --- MMA layer 2: Hh*Wh + Hl*Wh ---
    if (wid == 0 && elect_one()) {
        for (int pass = 0; pass < 2; ++pass) {
            uint32_t abase = sb + (pass ? SMEM_AL : SMEM_AH);
            for (int c = 0; c < 2; ++c) {
                uint64_t ad = smem_desc(abase + c * 16384);
                uint64_t bd = smem_desc(sb + SMEM_W + c * 16384);
                for (int k = 0; k < 4; ++k)
                    mma_f16_ss(tD2, ad + k * 2, bd + k * 2,
                               (pass == 0 && c == 0 && k == 0) ? 0u : 1u);
            }
        }
        TCGEN05_COMMIT(sb + SMEM_MBAR);
    }
    MBARRIER_WAIT_PARITY(sb + SMEM_MBAR, 0);

    // --- swap to W2 lo, Hh*Wl ---
    {
        const uint4* src = reinterpret_cast<const uint4*>(g_W2l);
        uint4* dst = reinterpret_cast<uint4*>(smem + SMEM_W);
        for (int i = tid; i < 2048; i += NT) dst[i] = src[i];
    }
    FENCE_ASYNC();
    __syncthreads();
    if (wid == 0 && elect_one()) {
        for (int c = 0; c < 2; ++c) {
            uint64_t ad = smem_desc(sb + SMEM_AH + c * 16384);
            uint64_t bd = smem_desc(sb + SMEM_W + c * 16384);
            for (int k = 0; k < 4; ++k)
                mma_f16_ss(tD2, ad + k * 2, bd + k * 2, 1u);
        }
        TCGEN05_COMMIT(sb + SMEM_MBAR);
    }
    MBARRIER_WAIT_PARITY(sb + SMEM_MBAR, 1);
    TCGEN05_FENCE_AFTER();

    // --- Epilogue 2: out = relu(D2+b2) . W3 + b3 ---
    if (wid < 4) {
        const int r = (wid << 5) + lane;
        const float* b2s = (const float*)(smem + SMEM_CONST + 512);
        const float* w3s = (const float*)(smem + SMEM_CONST + 1024);
        float acc = 0.0f;
        for (int ch = 0; ch < 4; ++ch) {
            uint32_t d[32];
            LDTM_X32(d, tD2 + ch * 32);
            TCGEN05_WAIT_LD();
            const int colbase = ch * 32;
#pragma unroll
            for (int j = 0; j < 32; ++j) {
                float h = fmaxf(__uint_as_float(d[j]) + b2s[colbase + j], 0.0f);
                acc = fmaf(h, w3s[colbase + j], acc);
            }
        }
        int e = e0 + r;
        if (e < E) out[e] = acc + ((const float*)(smem + SMEM_CONST + 1536))[0];
    }

    __syncthreads();
    if (tid == 0) MBARRIER_INVAL(sb + SMEM_MBAR);
    if (wid == 0) TCGEN05_DEALLOC(tmem, 256);

#else
    // ========================= FFMA2 fallback path ==========================
    float* smem = (float*)smem_raw;
    float* sWbuf0 = smem + SA_FLOATS;
    float* sWbuf1 = smem + SA_FLOATS + SW_FLOATS;

    const int tid  = threadIdx.x;
    const int lane = tid & 31;
    const int wrp  = tid >> 5;
    const int tx   = tid & 15;
    const int ty   = tid >> 4;
    const int rowbase = ty * 8;
    const int colbase = tx * 8;
    const long long e0 = (long long)blockIdx.x * TILE_M;
    const int wr = tid >> 4;
    const int wc = (tid & 15) * 8;

    for (int m = wrp; m < TILE_M; m += 8) {
        long long e = e0 + m;
        if (e < E) {
            long long s = ei[e];
            long long t = ei[(long long)E + e];
            float4 v1 = reinterpret_cast<const float4*>(x1 + s * 128)[lane];
            float4 v2 = reinterpret_cast<const float4*>(x2 + t * 128)[lane];
            reinterpret_cast<float4*>(smem + m * SA_LD)[lane]       = v1;
            reinterpret_cast<float4*>(smem + m * SA_LD + 128)[lane] = v2;
        }
    }

    float4 s0 = *reinterpret_cast<const float4*>(W1g + wr * 128 + wc);
    float4 s1 = *reinterpret_cast<const float4*>(W1g + wr * 128 + wc + 4);
    *reinterpret_cast<float4*>(sWbuf0 + wr * 128 + wc)     = s0;
    *reinterpret_cast<float4*>(sWbuf0 + wr * 128 + wc + 4) = s1;
    __syncthreads();

    ull acc[8][4];
#pragma unroll
    for (int i = 0; i < 8; ++i)
#pragma unroll
        for (int j = 0; j < 4; ++j) acc[i][j] = 0ULL;

    const float* aBase = smem + rowbase * SA_LD;
    for (int ct = 0; ct < 16; ++ct) {
        if (ct + 1 < 16) {
            const float* src = W1g + (ct + 1) * 16 * 128;
            s0 = *reinterpret_cast<const float4*>(src + wr * 128 + wc);
            s1 = *reinterpret_cast<const float4*>(src + wr * 128 + wc + 4);
        }
        gemm_chunk16<SA_LD>(aBase, ct * 16, (ct & 1) ? sWbuf1 : sWbuf0, colbase, acc);
        if (ct + 1 < 16) {
            float* dst = ((ct + 1) & 1) ? sWbuf1 : sWbuf0;
            *reinterpret_cast<float4*>(dst + wr * 128 + wc)     = s0;
            *reinterpret_cast<float4*>(dst + wr * 128 + wc + 4) = s1;
        }
        __syncthreads();
    }

    float* sH = smem;
    {
        float2 bb[4];
#pragma unroll
        for (int j = 0; j < 4; ++j)
            bb[j] = *reinterpret_cast<const float2*>(b1g + colbase + 2 * j);
#pragma unroll
        for (int i = 0; i < 8; ++i) {
            float* hrow = sH + (rowbase + i) * SH_LD + colbase;
#pragma unroll
            for (int j = 0; j < 4; ++j) {
                float2 v = unpack2(acc[i][j]);
                v.x = fmaxf(v.x + bb[j].x, 0.0f);
                v.y = fmaxf(v.y + bb[j].y, 0.0f);
                *reinterpret_cast<float2*>(hrow + 2 * j) = v;
            }
        }
    }

    s0 = *reinterpret_cast<const float4*>(W2g + wr * 128 + wc);
    s1 = *reinterpret_cast<const float4*>(W2g + wr * 128 + wc + 4);
    *reinterpret_cast<float4*>(sWbuf0 + wr * 128 + wc)     = s0;
    *reinterpret_cast<float4*>(sWbuf0 + wr * 128 + wc + 4) = s1;
    __syncthreads();

#pragma unroll
    for (int i = 0; i < 8; ++i)
#pragma unroll
        for (int j = 0; j < 4; ++j) acc[i][j] = 0ULL;

    const float* aBase2 = sH + rowbase * SH_LD;
    for (int ct = 0; ct < 8; ++ct) {
        if (ct + 1 < 8) {
            const float* src = W2g + (ct + 1) * 16 * 128;
            s0 = *reinterpret_cast<const float4*>(src + wr * 128 + wc);
            s1 = *reinterpret_cast<const float4*>(src + wr * 128 + wc + 4);
        }
        gemm_chunk16<SH_LD>(aBase2, ct * 16, (ct & 1) ? sWbuf1 : sWbuf0, colbase, acc);
        if (ct + 1 < 8) {
            float* dst = ((ct + 1) & 1) ? sWbuf1 : sWbuf0;
            *reinterpret_cast<float4*>(dst + wr * 128 + wc)     = s0;
            *reinterpret_cast<float4*>(dst + wr * 128 + wc + 4) = s1;
        }
        __syncthreads();
    }

    float2 b2v[4], w3v[4];
#pragma unroll
    for (int j = 0; j < 4; ++j) {
        b2v[j] = *reinterpret_cast<const float2*>(b2g + colbase + 2 * j);
        w3v[j] = *reinterpret_cast<const float2*>(W3g + colbase + 2 * j);
    }
    float p[8];
#pragma unroll
    for (int i = 0; i < 8; ++i) {
        float acc_p = 0.0f;
#pragma unroll
        for (int j = 0; j < 4; ++j) {
            float2 v = unpack2(acc[i][j]);
            float h0  = fmaxf(v.x + b2v[j].x, 0.0f);
            float h1v = fmaxf(v.y + b2v[j].y, 0.0f);
            acc_p += h0 * w3v[j].x + h1v * w3v[j].y;
        }
        p[i] = acc_p;
    }

    float* sRed = smem + SA_FLOATS;
#pragma unroll
    for (int i = 0; i < 8; ++i)
        sRed[(rowbase + i) * 17 + tx] = p[i];
    __syncthreads();

    if (tid < TILE_M) {
        long long e = e0 + tid;
        if (e < E) {
            float s = 0.0f;
#pragma unroll
            for (int t = 0; t < 16; ++t) s += sRed[tid * 17 + t];
            out[e] = s + b3g[0];
        }
    }
#endif
}

extern "C" void kernel_launch(void* const* d_in, const int* in_sizes, int n_in,
                              void* d_out, int out_size) {
    const float* x1 = (const float*)d_in[0];
    const float* x2 = (const float*)d_in[1];
    const int*   ei = (const int*)d_in[2];
    const float* W1 = (const float*)d_in[3];
    const float* b1 = (const float*)d_in[4];
    const float* W2 = (const float*)d_in[5];
    const float* b2 = (const float*)d_in[6];
    const float* W3 = (const float*)d_in[7];
    const float* b3 = (const float*)d_in[8];
    float*       out = (float*)d_out;

    int E = in_sizes[2] / 2;
    int grid = (E + TILE_M - 1) / TILE_M;

    prep_kernel<<<192, 256>>>(W1, W2);

    cudaFuncSetAttribute(edge_mlp_kernel,
                         cudaFuncAttributeMaxDynamicSharedMemorySize, SMEM_TOTAL);
    edge_mlp_kernel<<<grid, NT, SMEM_TOTAL>>>(x1, x2, ei, W1, b1, W2, b2, W3, b3,
                                              out, E);
}

// round 7
// speedup vs baseline: 4.8818x; 2.4896x over previous
#include <cuda_runtime.h>
#include <cuda_bf16.h>
#include <cstdint>

// ---------------------------------------------------------------------------
// Fused edge-MLP, persistent-CTA tcgen05 version.
//   pair = [x1[src], x2[dst]] (128 x 256/tile), 3-layer MLP fused.
// sm_103a path: TS-mode tcgen05 (A in TMEM), bf16 2-term split
//   (Ah*Wh + Al*Wh + Ah*Wl) for fp32-class accuracy. All weights resident in
//   SMEM (192KB) for the whole kernel; 148 persistent CTAs loop over tiles.
// TMEM map (512 cols): A 0-255 | D1/H 256-383 | D2 384-511.
// Fallback (plain sm_103 compile pass): FFMA2 kernel in a persistent loop.
// ---------------------------------------------------------------------------

#if defined(__CUDA_ARCH__) && defined(__CUDA_ARCH_FEAT_SM103_ALL)
#define EDGE_USE_TC 1
#else
#define EDGE_USE_TC 0
#endif

using ull = unsigned long long;

#define NT      256
#define TILE_M  128
#define GRID    148

// idesc kind::f16: F32 accum, BF16 a/b, N=128, M=128
#define IDESC   0x8200490u

// tc-path SMEM byte offsets
#define SMEM_W1H     0         // 64KB  (4 chunk-blocks of [128 x 64bf16] SW128)
#define SMEM_W1L     65536     // 64KB
#define SMEM_W2H     131072    // 32KB  (2 chunk-blocks)
#define SMEM_W2L     163840    // 32KB
#define SMEM_CONST   196608    // b1[128] | b2[128] | W3[128] | b3
#define SMEM_TMEMPTR 198160
#define SMEM_MBAR0   198168
#define SMEM_MBAR1   198176
#define SMEM_TOTAL   198208

// fallback-path SMEM layout (floats)
#define SA_LD    256
#define SH_LD    136
#define SA_FLOATS (128 * 256)
#define SW_FLOATS (16 * 128)

// Prepared weights (transposed to [N,K] rows, bf16 hi/lo, SW128 chunk blocks)
__device__ __align__(16) __nv_bfloat16 g_W1h[32768];
__device__ __align__(16) __nv_bfloat16 g_W1l[32768];
__device__ __align__(16) __nv_bfloat16 g_W2h[16384];
__device__ __align__(16) __nv_bfloat16 g_W2l[16384];

__device__ __forceinline__ int sw128(int off) { return off ^ ((off >> 3) & 0x70); }

// =================== helpers: fallback (all targets) =======================

__device__ __forceinline__ void fma2(ull& d, ull a, ull b) {
    asm("fma.rn.f32x2 %0, %1, %2, %0;" : "+l"(d) : "l"(a), "l"(b));
}
__device__ __forceinline__ ull dup2(float a) {
    ull d;
    asm("mov.b64 %0, {%1, %1};" : "=l"(d) : "f"(a));
    return d;
}
__device__ __forceinline__ float2 unpack2(ull v) {
    float2 f;
    asm("mov.b64 {%0, %1}, %2;" : "=f"(f.x), "=f"(f.y) : "l"(v));
    return f;
}

template <int LD>
__device__ __forceinline__ void gemm_chunk16(const float* __restrict__ aBase,
                                             int kt, const float* __restrict__ sw,
                                             int colbase, ull acc[8][4]) {
#pragma unroll
    for (int k = 0; k < 16; ++k) {
        ull a2[8];
#pragma unroll
        for (int i = 0; i < 8; ++i)
            a2[i] = dup2(aBase[i * LD + kt + k]);
        const ull* bp = reinterpret_cast<const ull*>(sw + k * 128 + colbase);
        ull b0 = bp[0], b1 = bp[1], b2 = bp[2], b3 = bp[3];
#pragma unroll
        for (int i = 0; i < 8; ++i) {
            fma2(acc[i][0], a2[i], b0);
            fma2(acc[i][1], a2[i], b1);
            fma2(acc[i][2], a2[i], b2);
            fma2(acc[i][3], a2[i], b3);
        }
    }
}

// =================== helpers: tcgen05 (sm_103a pass only) ==================

#if EDGE_USE_TC

__device__ __forceinline__ uint32_t smem_u32_of(const void* p) {
    uint32_t a;
    asm("{ .reg .u64 t; cvta.to.shared.u64 t, %1; cvt.u32.u64 %0, t; }"
        : "=r"(a) : "l"(p));
    return a;
}
__device__ __forceinline__ uint32_t elect_one() {
    uint32_t pred;
    asm volatile("{ .reg .pred p; elect.sync _|p, 0xFFFFFFFF; selp.b32 %0, 1, 0, p; }"
                 : "=r"(pred));
    return pred;
}
__device__ __forceinline__ uint64_t smem_desc(uint32_t addr) {
    // SW128, Blackwell version=1, SBO=64, LBO=1
    return 0x4000404000010000ULL | ((uint64_t)(addr >> 4) & 0x3FFF);
}
// TS-mode MMA: A in TMEM, B in SMEM
__device__ __forceinline__ void mma_f16_ts(uint32_t d_tmem, uint32_t a_tmem,
                                           uint64_t b_desc, uint32_t en) {
    asm volatile(
        "{\n\t.reg .pred p;\n\tsetp.ne.u32 p, %4, 0;\n\t"
        "tcgen05.mma.cta_group::1.kind::f16 [%0], [%1], %2, %3, {%5,%5,%5,%5}, p;\n\t}"
        :: "r"(d_tmem), "r"(a_tmem), "l"(b_desc), "r"(IDESC), "r"(en), "r"(0u)
        : "memory");
}

#define TCGEN05_ALLOC(sa, n) \
    asm volatile("tcgen05.alloc.cta_group::1.sync.aligned.shared::cta.b32 [%0], %1;" \
                 :: "r"((uint32_t)(sa)), "r"((uint32_t)(n)) : "memory")
#define TCGEN05_DEALLOC(t, n) \
    asm volatile("tcgen05.dealloc.cta_group::1.sync.aligned.b32 %0, %1;" \
                 :: "r"(t), "r"((uint32_t)(n)))
#define TCGEN05_COMMIT(mb) \
    asm volatile("tcgen05.commit.cta_group::1.mbarrier::arrive::one.shared::cluster.b64 [%0];" \
                 :: "r"((uint32_t)(mb)) : "memory")
#define TCGEN05_WAIT_LD()  asm volatile("tcgen05.wait::ld.sync.aligned;" ::: "memory")
#define TCGEN05_WAIT_ST()  asm volatile("tcgen05.wait::st.sync.aligned;" ::: "memory")
#define TCGEN05_FENCE_BEFORE() asm volatile("tcgen05.fence::before_thread_sync;" ::: "memory")
#define TCGEN05_FENCE_AFTER()  asm volatile("tcgen05.fence::after_thread_sync;" ::: "memory")
#define FENCE_ASYNC() asm volatile("fence.proxy.async.shared::cta;" ::: "memory")
#define MBARRIER_INIT(mb, c) \
    asm volatile("mbarrier.init.shared.b64 [%0], %1;" :: "r"((uint32_t)(mb)), "r"((uint32_t)(c)) : "memory")
#define MBARRIER_INVAL(mb) \
    asm volatile("mbarrier.inval.shared.b64 [%0];" :: "r"((uint32_t)(mb)) : "memory")

#define MBARRIER_WAIT_PARITY(mb, ph) do {                                          \
    uint32_t _m = (uint32_t)(mb), _p = (uint32_t)(ph), _done;                      \
    asm volatile("{\n\t.reg .pred p;\n\t"                                          \
        "mbarrier.try_wait.parity.acquire.cta.shared::cta.b64 p, [%1], %2;\n\t"    \
        "selp.b32 %0, 1, 0, p;\n\t}" : "=r"(_done) : "r"(_m), "r"(_p) : "memory"); \
    if (!_done) {                                                                  \
        asm volatile("{\n\t.reg .pred P1;\n\t"                                     \
        "WL_%=:\n\t"                                                               \
        "mbarrier.try_wait.parity.acquire.cta.shared::cta.b64 P1, [%0], %1, 0x989680;\n\t" \
        "@P1 bra.uni WD_%=;\n\t"                                                   \
        "bra.uni WL_%=;\n\t"                                                       \
        "WD_%=:\n\t}" :: "r"(_m), "r"(_p) : "memory");                             \
    }                                                                              \
} while (0)

#define LDTM_X32(r, a)                                                             \
    asm volatile("tcgen05.ld.sync.aligned.32x32b.x32.b32 "                         \
        "{%0,%1,%2,%3,%4,%5,%6,%7,%8,%9,%10,%11,%12,%13,%14,%15,"                  \
        "%16,%17,%18,%19,%20,%21,%22,%23,%24,%25,%26,%27,%28,%29,%30,%31}, [%32];" \
        : "=r"((r)[0]),"=r"((r)[1]),"=r"((r)[2]),"=r"((r)[3]),                     \
          "=r"((r)[4]),"=r"((r)[5]),"=r"((r)[6]),"=r"((r)[7]),                     \
          "=r"((r)[8]),"=r"((r)[9]),"=r"((r)[10]),"=r"((r)[11]),                   \
          "=r"((r)[12]),"=r"((r)[13]),"=r"((r)[14]),"=r"((r)[15]),                 \
          "=r"((r)[16]),"=r"((r)[17]),"=r"((r)[18]),"=r"((r)[19]),                 \
          "=r"((r)[20]),"=r"((r)[21]),"=r"((r)[22]),"=r"((r)[23]),                 \
          "=r"((r)[24]),"=r"((r)[25]),"=r"((r)[26]),"=r"((r)[27]),                 \
          "=r"((r)[28]),"=r"((r)[29]),"=r"((r)[30]),"=r"((r)[31])                  \
        : "r"(a))

#define STTM_X16(a, r)                                                             \
    asm volatile("tcgen05.st.sync.aligned.32x32b.x16.b32 [%0], "                   \
        "{%1,%2,%3,%4,%5,%6,%7,%8,%9,%10,%11,%12,%13,%14,%15,%16};"                \
        :: "r"(a),                                                                 \
           "r"((r)[0]),"r"((r)[1]),"r"((r)[2]),"r"((r)[3]),                        \
           "r"((r)[4]),"r"((r)[5]),"r"((r)[6]),"r"((r)[7]),                        \
           "r"((r)[8]),"r"((r)[9]),"r"((r)[10]),"r"((r)[11]),                      \
           "r"((r)[12]),"r"((r)[13]),"r"((r)[14]),"r"((r)[15])                     \
        : "memory")

__device__ __forceinline__ uint32_t pack_bf2(float lo_val, float hi_val) {
    __nv_bfloat162 t = __floats2bfloat162_rn(lo_val, hi_val);
    return *reinterpret_cast<uint32_t*>(&t);
}

#endif  // EDGE_USE_TC

// ------------------------------ prep kernel -------------------------------
__global__ void prep_kernel(const float* __restrict__ W1,
                            const float* __restrict__ W2) {
    int i = blockIdx.x * blockDim.x + threadIdx.x;
    if (i < 32768) {
        int k = i >> 7, n = i & 127;
        float w = W1[i];
        __nv_bfloat16 hi = __float2bfloat16_rn(w);
        __nv_bfloat16 lo = __float2bfloat16_rn(w - __bfloat162float(hi));
        int c = k >> 6, kk = k & 63;
        int idx = (c * 16384 + sw128(n * 128 + kk * 2)) >> 1;
        g_W1h[idx] = hi;
        g_W1l[idx] = lo;
    } else if (i < 49152) {
        int j = i - 32768;
        int k = j >> 7, n = j & 127;
        float w = W2[j];
        __nv_bfloat16 hi = __float2bfloat16_rn(w);
        __nv_bfloat16 lo = __float2bfloat16_rn(w - __bfloat162float(hi));
        int c = k >> 6, kk = k & 63;
        int idx = (c * 16384 + sw128(n * 128 + kk * 2)) >> 1;
        g_W2h[idx] = hi;
        g_W2l[idx] = lo;
    }
}

// ------------------------------ main kernel -------------------------------

__global__ __launch_bounds__(NT, 1)
void edge_mlp_kernel(const float* __restrict__ x1,
                     const float* __restrict__ x2,
                     const int* __restrict__ ei,
                     const float* __restrict__ W1g, const float* __restrict__ b1g,
                     const float* __restrict__ W2g, const float* __restrict__ b2g,
                     const float* __restrict__ W3g, const float* __restrict__ b3g,
                     float* __restrict__ out, int E) {
    extern __shared__ char smem_raw[];
    const int ntiles = (E + TILE_M - 1) / TILE_M;

#if EDGE_USE_TC
    // ==================== persistent tcgen05 TS-mode path ===================
    char* smem = smem_raw;
    const uint32_t sb = smem_u32_of(smem);
    const int tid  = threadIdx.x;
    const int lane = tid & 31;
    const int wid  = tid >> 5;
    const int sp   = wid & 3;                 // TMEM subpartition
    const int r    = sp * 32 + lane;          // row within tile
    const uint32_t rowbits = (uint32_t)sp << 21;

    if (wid == 0) TCGEN05_ALLOC(sb + SMEM_TMEMPTR, 512);
    if (tid == 0) { MBARRIER_INIT(sb + SMEM_MBAR0, 1); MBARRIER_INIT(sb + SMEM_MBAR1, 1); }
    __syncthreads();
    uint32_t tmem;
    asm volatile("ld.shared.b32 %0, [%1];" : "=r"(tmem) : "r"(sb + SMEM_TMEMPTR));
    const uint32_t tD1 = tmem + 256, tD2 = tmem + 384;

    // ---- one-time: stage all weights (192KB) + consts into SMEM ----
    {
        const uint4* s1 = reinterpret_cast<const uint4*>(g_W1h);
        const uint4* s2 = reinterpret_cast<const uint4*>(g_W1l);
        const uint4* s3 = reinterpret_cast<const uint4*>(g_W2h);
        const uint4* s4 = reinterpret_cast<const uint4*>(g_W2l);
        uint4* d1 = reinterpret_cast<uint4*>(smem + SMEM_W1H);
        uint4* d2 = reinterpret_cast<uint4*>(smem + SMEM_W1L);
        uint4* d3 = reinterpret_cast<uint4*>(smem + SMEM_W2H);
        uint4* d4 = reinterpret_cast<uint4*>(smem + SMEM_W2L);
        for (int i = tid; i < 4096; i += NT) { d1[i] = s1[i]; d2[i] = s2[i]; }
        for (int i = tid; i < 2048; i += NT) { d3[i] = s3[i]; d4[i] = s4[i]; }
        if (tid < 128) {
            ((float*)(smem + SMEM_CONST))[tid]        = b1g[tid];
            ((float*)(smem + SMEM_CONST + 512))[tid]  = b2g[tid];
            ((float*)(smem + SMEM_CONST + 1024))[tid] = W3g[tid];
        }
        if (tid == 0) ((float*)(smem + SMEM_CONST + 1536))[0] = b3g[0];
    }
    FENCE_ASYNC();
    __syncthreads();

    const float* b1s = (const float*)(smem + SMEM_CONST);
    const float* b2s = (const float*)(smem + SMEM_CONST + 512);
    const float* w3s = (const float*)(smem + SMEM_CONST + 1024);

    int prev_t = -1;
    int iter = 0;

    for (int t = blockIdx.x; t < ntiles; t += GRID) {
        // ---------- G: gather + bf16 split + STTM A (all 8 warps) ----------
        // warps 0-3: x1 half (k 0..127 -> Ah cols 0-63, Al 128-191)
        // warps 4-7: x2 half (k 128..255 -> Ah cols 64-127, Al 192-255)
        {
            int e = t * TILE_M + r;
            const float* rowp = nullptr;
            if (e < E) {
                int node = (wid < 4) ? ei[e] : ei[E + e];
                rowp = ((wid < 4) ? x1 : x2) + (long long)node * 128;
            }
            const int hi_col = (wid < 4) ? 0 : 64;
#pragma unroll
            for (int q = 0; q < 4; ++q) {           // 32 floats per quarter
                float4 v[8];
                if (rowp) {
#pragma unroll
                    for (int i = 0; i < 8; ++i)
                        v[i] = reinterpret_cast<const float4*>(rowp + q * 32)[i];
                } else {
#pragma unroll
                    for (int i = 0; i < 8; ++i) v[i] = make_float4(0.f, 0.f, 0.f, 0.f);
                }
                uint32_t hw[16], lw[16];
#pragma unroll
                for (int i = 0; i < 8; ++i) {
                    __nv_bfloat162 h0 = __floats2bfloat162_rn(v[i].x, v[i].y);
                    __nv_bfloat162 h1 = __floats2bfloat162_rn(v[i].z, v[i].w);
                    hw[2 * i]     = *reinterpret_cast<uint32_t*>(&h0);
                    hw[2 * i + 1] = *reinterpret_cast<uint32_t*>(&h1);
                    lw[2 * i]     = pack_bf2(v[i].x - __bfloat162float(h0.x),
                                             v[i].y - __bfloat162float(h0.y));
                    lw[2 * i + 1] = pack_bf2(v[i].z - __bfloat162float(h1.x),
                                             v[i].w - __bfloat162float(h1.y));
                }
                STTM_X16(tmem + hi_col + q * 16 + rowbits, hw);
                STTM_X16(tmem + 128 + hi_col + q * 16 + rowbits, lw);
            }
            TCGEN05_WAIT_ST();
        }

        // chain-2(t-1) must be fully done before chain-1(t) overwrites D1/H
        if (iter > 0) MBARRIER_WAIT_PARITY(sb + SMEM_MBAR1, (iter - 1) & 1);
        TCGEN05_FENCE_BEFORE();
        __syncthreads();

        // ---------- issue chain-1 (warp 4): 3 products x 16 K16-steps ------
        if (wid == 4 && elect_one()) {
            TCGEN05_FENCE_AFTER();
#pragma unroll
            for (int pass = 0; pass < 3; ++pass) {
                const uint32_t acol = (pass == 1) ? 128u : 0u;
                const uint32_t wbase = (pass == 2) ? SMEM_W1L : SMEM_W1H;
                for (int c = 0; c < 4; ++c) {
                    uint64_t bd = smem_desc(sb + wbase + c * 16384);
                    for (int k = 0; k < 4; ++k)
                        mma_f16_ts(tD1, tmem + acol + (c * 4 + k) * 8, bd + k * 2,
                                   (pass == 0 && c == 0 && k == 0) ? 0u : 1u);
                }
            }
            TCGEN05_COMMIT(sb + SMEM_MBAR0);
        }

        // ---------- epilogue-2 of previous tile (warps 0-3, ∥ chain-1) -----
        if (iter > 0 && wid < 4) {
            TCGEN05_FENCE_AFTER();
            float acc = 0.0f;
#pragma unroll
            for (int j = 0; j < 4; ++j) {
                uint32_t d[32];
                LDTM_X32(d, tD2 + 32 * j);
                TCGEN05_WAIT_LD();
#pragma unroll
                for (int p = 0; p < 32; ++p) {
                    int col = 32 * j + p;
                    float h = fmaxf(__uint_as_float(d[p]) + b2s[col], 0.0f);
                    acc = fmaf(h, w3s[col], acc);
                }
            }
            int e = prev_t * TILE_M + r;
            if (e < E) out[e] = acc + ((const float*)(smem + SMEM_CONST + 1536))[0];
        }

        // ---------- wait chain-1, epilogue-1: H = split(relu(D1+b1)) -------
        MBARRIER_WAIT_PARITY(sb + SMEM_MBAR0, iter & 1);
        TCGEN05_FENCE_AFTER();
        if (wid < 4) {
            uint32_t hl[64];
#pragma unroll
            for (int j = 0; j < 4; ++j) {
                uint32_t d[32];
                LDTM_X32(d, tD1 + 32 * j);
                TCGEN05_WAIT_LD();
                uint32_t hw[16];
#pragma unroll
                for (int p = 0; p < 16; ++p) {
                    int col = 32 * j + 2 * p;
                    float v0 = fmaxf(__uint_as_float(d[2 * p])     + b1s[col],     0.0f);
                    float v1 = fmaxf(__uint_as_float(d[2 * p + 1]) + b1s[col + 1], 0.0f);
                    __nv_bfloat162 h = __floats2bfloat162_rn(v0, v1);
                    hw[p] = *reinterpret_cast<uint32_t*>(&h);
                    hl[16 * j + p] = pack_bf2(v0 - __bfloat162float(h.x),
                                              v1 - __bfloat162float(h.y));
                }
                // Hh cols 256+16j..+15 — always within already-read D1 cols
                STTM_X16(tmem + 256 + 16 * j + rowbits, hw);
            }
#pragma unroll
            for (int j = 0; j < 4; ++j)
                STTM_X16(tmem + 320 + 16 * j + rowbits, &hl[16 * j]);
            TCGEN05_WAIT_ST();
        }
        TCGEN05_FENCE_BEFORE();
        __syncthreads();

        // ---------- issue chain-2 (warp 4): 3 products x 8 K16-steps -------
        if (wid == 4 && elect_one()) {
            TCGEN05_FENCE_AFTER();
#pragma unroll
            for (int pass = 0; pass < 3; ++pass) {
                const uint32_t acol = (pass == 1) ? 320u : 256u;
                const uint32_t wbase = (pass == 2) ? SMEM_W2L : SMEM_W2H;
                for (int c = 0; c < 2; ++c) {
                    uint64_t bd = smem_desc(sb + wbase + c * 16384);
                    for (int k = 0; k < 4; ++k)
                        mma_f16_ts(tD2, tmem + acol + (c * 4 + k) * 8, bd + k * 2,
                                   (pass == 0 && c == 0 && k == 0) ? 0u : 1u);
                }
            }
            TCGEN05_COMMIT(sb + SMEM_MBAR1);
        }

        prev_t = t;
        ++iter;
    }

    // ---------- drain: final epilogue-2 ----------
    if (prev_t >= 0) {
        MBARRIER_WAIT_PARITY(sb + SMEM_MBAR1, (iter - 1) & 1);
        TCGEN05_FENCE_AFTER();
        if (wid < 4) {
            float acc = 0.0f;
#pragma unroll
            for (int j = 0; j < 4; ++j) {
                uint32_t d[32];
                LDTM_X32(d, tD2 + 32 * j);
                TCGEN05_WAIT_LD();
#pragma unroll
                for (int p = 0; p < 32; ++p) {
                    int col = 32 * j + p;
                    float h = fmaxf(__uint_as_float(d[p]) + b2s[col], 0.0f);
                    acc = fmaf(h, w3s[col], acc);
                }
            }
            int e = prev_t * TILE_M + r;
            if (e < E) out[e] = acc + ((const float*)(smem + SMEM_CONST + 1536))[0];
        }
    }

    __syncthreads();
    if (tid == 0) { MBARRIER_INVAL(sb + SMEM_MBAR0); MBARRIER_INVAL(sb + SMEM_MBAR1); }
    __syncthreads();
    if (wid == 0) TCGEN05_DEALLOC(tmem, 512);

#else
    // ================= FFMA2 fallback path (persistent loop) ================
    float* smem = (float*)smem_raw;
    float* sWbuf0 = smem + SA_FLOATS;
    float* sWbuf1 = smem + SA_FLOATS + SW_FLOATS;

    const int tid  = threadIdx.x;
    const int lane = tid & 31;
    const int wrp  = tid >> 5;
    const int tx   = tid & 15;
    const int ty   = tid >> 4;
    const int rowbase = ty * 8;
    const int colbase = tx * 8;
    const int wr = tid >> 4;
    const int wc = (tid & 15) * 8;

    for (int tt = blockIdx.x; tt < ntiles; tt += GRID) {
        const long long e0 = (long long)tt * TILE_M;

        for (int m = wrp; m < TILE_M; m += 8) {
            long long e = e0 + m;
            if (e < E) {
                long long s = ei[e];
                long long t2 = ei[(long long)E + e];
                float4 v1 = reinterpret_cast<const float4*>(x1 + s * 128)[lane];
                float4 v2 = reinterpret_cast<const float4*>(x2 + t2 * 128)[lane];
                reinterpret_cast<float4*>(smem + m * SA_LD)[lane]       = v1;
                reinterpret_cast<float4*>(smem + m * SA_LD + 128)[lane] = v2;
            }
        }

        float4 s0 = *reinterpret_cast<const float4*>(W1g + wr * 128 + wc);
        float4 s1 = *reinterpret_cast<const float4*>(W1g + wr * 128 + wc + 4);
        *reinterpret_cast<float4*>(sWbuf0 + wr * 128 + wc)     = s0;
        *reinterpret_cast<float4*>(sWbuf0 + wr * 128 + wc + 4) = s1;
        __syncthreads();

        ull acc[8][4];
#pragma unroll
        for (int i = 0; i < 8; ++i)
#pragma unroll
            for (int j = 0; j < 4; ++j) acc[i][j] = 0ULL;

        const float* aBase = smem + rowbase * SA_LD;
        for (int ct = 0; ct < 16; ++ct) {
            if (ct + 1 < 16) {
                const float* src = W1g + (ct + 1) * 16 * 128;
                s0 = *reinterpret_cast<const float4*>(src + wr * 128 + wc);
                s1 = *reinterpret_cast<const float4*>(src + wr * 128 + wc + 4);
            }
            gemm_chunk16<SA_LD>(aBase, ct * 16, (ct & 1) ? sWbuf1 : sWbuf0, colbase, acc);
            if (ct + 1 < 16) {
                float* dst = ((ct + 1) & 1) ? sWbuf1 : sWbuf0;
                *reinterpret_cast<float4*>(dst + wr * 128 + wc)     = s0;
                *reinterpret_cast<float4*>(dst + wr * 128 + wc + 4) = s1;
            }
            __syncthreads();
        }

        float* sH = smem;
        {
            float2 bb[4];
#pragma unroll
            for (int j = 0; j < 4; ++j)
                bb[j] = *reinterpret_cast<const float2*>(b1g + colbase + 2 * j);
#pragma unroll
            for (int i = 0; i < 8; ++i) {
                float* hrow = sH + (rowbase + i) * SH_LD + colbase;
#pragma unroll
                for (int j = 0; j < 4; ++j) {
                    float2 v = unpack2(acc[i][j]);
                    v.x = fmaxf(v.x + bb[j].x, 0.0f);
                    v.y = fmaxf(v.y + bb[j].y, 0.0f);
                    *reinterpret_cast<float2*>(hrow + 2 * j) = v;
                }
            }
        }

        s0 = *reinterpret_cast<const float4*>(W2g + wr * 128 + wc);
        s1 = *reinterpret_cast<const float4*>(W2g + wr * 128 + wc + 4);
        *reinterpret_cast<float4*>(sWbuf0 + wr * 128 + wc)     = s0;
        *reinterpret_cast<float4*>(sWbuf0 + wr * 128 + wc + 4) = s1;
        __syncthreads();

#pragma unroll
        for (int i = 0; i < 8; ++i)
#pragma unroll
            for (int j = 0; j < 4; ++j) acc[i][j] = 0ULL;

        const float* aBase2 = sH + rowbase * SH_LD;
        for (int ct = 0; ct < 8; ++ct) {
            if (ct + 1 < 8) {
                const float* src = W2g + (ct + 1) * 16 * 128;
                s0 = *reinterpret_cast<const float4*>(src + wr * 128 + wc);
                s1 = *reinterpret_cast<const float4*>(src + wr * 128 + wc + 4);
            }
            gemm_chunk16<SH_LD>(aBase2, ct * 16, (ct & 1) ? sWbuf1 : sWbuf0, colbase, acc);
            if (ct + 1 < 8) {
                float* dst = ((ct + 1) & 1) ? sWbuf1 : sWbuf0;
                *reinterpret_cast<float4*>(dst + wr * 128 + wc)     = s0;
                *reinterpret_cast<float4*>(dst + wr * 128 + wc + 4) = s1;
            }
            __syncthreads();
        }

        float2 b2v[4], w3v[4];
#pragma unroll
        for (int j = 0; j < 4; ++j) {
            b2v[j] = *reinterpret_cast<const float2*>(b2g + colbase + 2 * j);
            w3v[j] = *reinterpret_cast<const float2*>(W3g + colbase + 2 * j);
        }
        float p[8];
#pragma unroll
        for (int i = 0; i < 8; ++i) {
            float acc_p = 0.0f;
#pragma unroll
            for (int j = 0; j < 4; ++j) {
                float2 v = unpack2(acc[i][j]);
                float h0  = fmaxf(v.x + b2v[j].x, 0.0f);
                float h1v = fmaxf(v.y + b2v[j].y, 0.0f);
                acc_p += h0 * w3v[j].x + h1v * w3v[j].y;
            }
            p[i] = acc_p;
        }

        float* sRed = smem + SA_FLOATS;
#pragma unroll
        for (int i = 0; i < 8; ++i)
            sRed[(rowbase + i) * 17 + tx] = p[i];
        __syncthreads();

        if (tid < TILE_M) {
            long long e = e0 + tid;
            if (e < E) {
                float s = 0.0f;
#pragma unroll
                for (int u = 0; u < 16; ++u) s += sRed[tid * 17 + u];
                out[e] = s + b3g[0];
            }
        }
        __syncthreads();
    }
#endif
}

extern "C" void kernel_launch(void* const* d_in, const int* in_sizes, int n_in,
                              void* d_out, int out_size) {
    const float* x1 = (const float*)d_in[0];
    const float* x2 = (const float*)d_in[1];
    const int*   ei = (const int*)d_in[2];
    const float* W1 = (const float*)d_in[3];
    const float* b1 = (const float*)d_in[4];
    const float* W2 = (const float*)d_in[5];
    const float* b2 = (const float*)d_in[6];
    const float* W3 = (const float*)d_in[7];
    const float* b3 = (const float*)d_in[8];
    float*       out = (float*)d_out;

    int E = in_sizes[2] / 2;

    prep_kernel<<<192, 256>>>(W1, W2);

    cudaFuncSetAttribute(edge_mlp_kernel,
                         cudaFuncAttributeMaxDynamicSharedMemorySize, SMEM_TOTAL);
    edge_mlp_kernel<<<GRID, NT, SMEM_TOTAL>>>(x1, x2, ei, W1, b1, W2, b2, W3, b3,
                                              out, E);
}